// round 2
// baseline (speedup 1.0000x reference)
#include <cuda_runtime.h>

#define N_NODES  100000
#define N_EDGES  1600000
#define HID      96
#define N_GRAPHS 2048

// ---------------- scratch (device globals; no allocation allowed) ----------
__device__ int   g_deg[N_NODES];
__device__ int   g_rowptr[N_NODES + 1];
__device__ int   g_cursor[N_NODES];
__device__ int   g_col[N_EDGES];
__device__ float g_dinv[N_NODES];
__device__ float g_bufA[N_NODES * HID];
__device__ float g_bufB[N_NODES * HID];
__device__ float g_pool[N_GRAPHS * HID];

// ---------------- CSR build ------------------------------------------------
__global__ __launch_bounds__(256) void zero_deg_kernel() {
    int i = blockIdx.x * blockDim.x + threadIdx.x;
    if (i < N_NODES) g_deg[i] = 0;
}

__global__ __launch_bounds__(256) void count_kernel(const int* __restrict__ ei) {
    int e = blockIdx.x * blockDim.x + threadIdx.x;
    if (e < N_EDGES) atomicAdd(&g_deg[ei[N_EDGES + e]], 1);
}

// single-block exclusive scan of g_deg -> g_rowptr  (N=100000, 1024 threads)
__global__ __launch_bounds__(1024) void scan_kernel() {
    __shared__ int part[1024];
    const int C = (N_NODES + 1023) / 1024;  // 98
    int t = threadIdx.x;
    int s = 0;
    for (int j = 0; j < C; j++) {
        int idx = t * C + j;
        if (idx < N_NODES) s += g_deg[idx];
    }
    part[t] = s;
    __syncthreads();
    // Hillis-Steele inclusive scan
    for (int off = 1; off < 1024; off <<= 1) {
        int v = (t >= off) ? part[t - off] : 0;
        __syncthreads();
        part[t] += v;
        __syncthreads();
    }
    int run = (t == 0) ? 0 : part[t - 1];
    for (int j = 0; j < C; j++) {
        int idx = t * C + j;
        if (idx < N_NODES) {
            g_rowptr[idx] = run;
            run += g_deg[idx];
        }
    }
    if (t == 1023) g_rowptr[N_NODES] = run;
}

__global__ __launch_bounds__(256) void dinv_cursor_kernel() {
    int i = blockIdx.x * blockDim.x + threadIdx.x;
    if (i < N_NODES) {
        g_dinv[i]   = rsqrtf((float)(g_deg[i] + 1));  // +1 self-loop
        g_cursor[i] = g_rowptr[i];
    }
}

__global__ __launch_bounds__(256) void fill_kernel(const int* __restrict__ ei) {
    int e = blockIdx.x * blockDim.x + threadIdx.x;
    if (e < N_EDGES) {
        int s = ei[e];
        int d = ei[N_EDGES + e];
        int pos = atomicAdd(&g_cursor[d], 1);
        g_col[pos] = s;
    }
}

// ---------------- xs0 = x * dinv  (32 features) -----------------------------
__global__ __launch_bounds__(256) void scale0_kernel(const float* __restrict__ x) {
    int idx = blockIdx.x * blockDim.x + threadIdx.x;   // float4 index
    if (idx < N_NODES * 8) {
        int node = idx >> 3;
        float d = g_dinv[node];
        float4 v = ((const float4*)x)[idx];
        v.x *= d; v.y *= d; v.z *= d; v.w *= d;
        ((float4*)g_bufA)[idx] = v;
    }
}

// ---------------- aggregation:  out = dinv * (xs + sum_{src} xs[src]) ------
// F4 = feature count / 4.  F4==8: 4 nodes per warp (8 lanes each).
//                          F4==24: 1 node per warp (24 active lanes).
template <int F4>
__global__ __launch_bounds__(256) void agg_kernel(const float* __restrict__ xs,
                                                  float* __restrict__ out) {
    int gtid = blockIdx.x * blockDim.x + threadIdx.x;
    int warp = gtid >> 5;
    int lane = threadIdx.x & 31;
    int node, f;
    if (F4 == 8) { node = warp * 4 + (lane >> 3); f = lane & 7; }
    else         { node = warp; f = lane; if (f >= F4) return; }
    if (node >= N_NODES) return;

    const float4* x4 = (const float4*)xs;
    float4 acc = x4[(long)node * F4 + f];   // self term
    int e0 = g_rowptr[node];
    int e1 = g_rowptr[node + 1];
    for (int e = e0; e < e1; e++) {
        int s = g_col[e];
        float4 v = __ldg(&x4[(long)s * F4 + f]);
        acc.x += v.x; acc.y += v.y; acc.z += v.z; acc.w += v.w;
    }
    float d = g_dinv[node];
    acc.x *= d; acc.y *= d; acc.z *= d; acc.w *= d;
    ((float4*)out)[(long)node * F4 + f] = acc;
}

// ---------------- GEMM: C[M,96] = relu(A[M,K] @ W[K,96] + b) (* dinv) ------
// 128 threads, 64-row tile, thread tile 8 rows x 6 cols, K chunked by 32.
template <int K, bool SCALE>
__global__ __launch_bounds__(128) void gemm_kernel(const float* __restrict__ A,
                                                   float* __restrict__ C,
                                                   const float* __restrict__ W,
                                                   const float* __restrict__ b) {
    __shared__ float sA[32 * 68];   // transposed [k][row], pad 68
    __shared__ float sW[32 * 96];
    const int tid  = threadIdx.x;
    const int row0 = blockIdx.x * 64;
    const int tx = tid & 15;   // col group: cols tx*6 .. tx*6+5
    const int ty = tid >> 4;   // row group: rows ty*8 .. ty*8+7

    float acc[8][6];
#pragma unroll
    for (int r = 0; r < 8; r++)
#pragma unroll
        for (int c = 0; c < 6; c++) acc[r][c] = 0.f;

    for (int kb = 0; kb < K; kb += 32) {
        for (int i = tid; i < 32 * 96; i += 128)
            sW[i] = W[(kb + i / 96) * 96 + (i % 96)];
        for (int i = tid; i < 64 * 32; i += 128) {
            int r = i >> 5, kl = i & 31;
            int gr = row0 + r;
            sA[kl * 68 + r] = (gr < N_NODES) ? A[(long)gr * K + kb + kl] : 0.f;
        }
        __syncthreads();
#pragma unroll 8
        for (int k = 0; k < 32; k++) {
            float4 a0 = *(const float4*)&sA[k * 68 + ty * 8];
            float4 a1 = *(const float4*)&sA[k * 68 + ty * 8 + 4];
            float2 w0 = *(const float2*)&sW[k * 96 + tx * 6];
            float2 w1 = *(const float2*)&sW[k * 96 + tx * 6 + 2];
            float2 w2 = *(const float2*)&sW[k * 96 + tx * 6 + 4];
            float av[8] = {a0.x, a0.y, a0.z, a0.w, a1.x, a1.y, a1.z, a1.w};
            float wv[6] = {w0.x, w0.y, w1.x, w1.y, w2.x, w2.y};
#pragma unroll
            for (int r = 0; r < 8; r++)
#pragma unroll
                for (int c = 0; c < 6; c++) acc[r][c] += av[r] * wv[c];
        }
        __syncthreads();
    }

    float bias[6];
#pragma unroll
    for (int c = 0; c < 6; c++) bias[c] = b[tx * 6 + c];
#pragma unroll
    for (int r = 0; r < 8; r++) {
        int row = row0 + ty * 8 + r;
        if (row < N_NODES) {
            float d = SCALE ? g_dinv[row] : 1.f;
            float* Cp = &C[(long)row * 96 + tx * 6];
#pragma unroll
            for (int c = 0; c < 6; c++) {
                float v = acc[r][c] + bias[c];
                v = fmaxf(v, 0.f);
                Cp[c] = v * d;
            }
        }
    }
}

// ---------------- global add pool (batch sorted -> run accumulation) -------
__global__ __launch_bounds__(256) void zero_pool_kernel() {
    int i = blockIdx.x * blockDim.x + threadIdx.x;
    if (i < N_GRAPHS * HID / 4) ((float4*)g_pool)[i] = make_float4(0.f, 0.f, 0.f, 0.f);
}

__global__ __launch_bounds__(256) void pool_kernel(const int* __restrict__ batch,
                                                   const float* __restrict__ h) {
    const int CH = 128;
    int warp = (blockIdx.x * blockDim.x + threadIdx.x) >> 5;
    int lane = threadIdx.x & 31;
    if (lane >= 24) return;
    int n0 = warp * CH;
    if (n0 >= N_NODES) return;
    int n1 = min(n0 + CH, N_NODES);

    const float4* h4 = (const float4*)h;
    int cur = batch[n0];
    float4 acc = make_float4(0.f, 0.f, 0.f, 0.f);
    for (int n = n0; n < n1; n++) {
        int bg = batch[n];
        if (bg != cur) {
            float* p = &g_pool[cur * HID + lane * 4];
            atomicAdd(p + 0, acc.x); atomicAdd(p + 1, acc.y);
            atomicAdd(p + 2, acc.z); atomicAdd(p + 3, acc.w);
            acc = make_float4(0.f, 0.f, 0.f, 0.f);
            cur = bg;
        }
        float4 v = h4[(long)n * 24 + lane];
        acc.x += v.x; acc.y += v.y; acc.z += v.z; acc.w += v.w;
    }
    float* p = &g_pool[cur * HID + lane * 4];
    atomicAdd(p + 0, acc.x); atomicAdd(p + 1, acc.y);
    atomicAdd(p + 2, acc.z); atomicAdd(p + 3, acc.w);
}

// ---------------- final MLP: relu(g@Wf1+bf1)@Wf2+bf2 -----------------------
__global__ __launch_bounds__(128) void mlp_kernel(const float* __restrict__ Wf1,
                                                  const float* __restrict__ bf1,
                                                  const float* __restrict__ Wf2,
                                                  const float* __restrict__ bf2,
                                                  float* __restrict__ out) {
    int g = blockIdx.x * 4 + (threadIdx.x >> 5);
    int j = threadIdx.x & 31;
    if (g >= N_GRAPHS) return;
    float hj = bf1[j];
    const float* gp = &g_pool[g * HID];
#pragma unroll 8
    for (int i = 0; i < 96; i++) hj += gp[i] * Wf1[i * 32 + j];
    hj = fmaxf(hj, 0.f);
    float v = hj * Wf2[j];
#pragma unroll
    for (int off = 16; off; off >>= 1) v += __shfl_down_sync(0xffffffffu, v, off);
    if (j == 0) out[g] = v + bf2[0];
}

// ---------------- launch ---------------------------------------------------
extern "C" void kernel_launch(void* const* d_in, const int* in_sizes, int n_in,
                              void* d_out, int out_size) {
    const float* x     = (const float*)d_in[0];
    const int*   ei    = (const int*)d_in[1];    // [2, E] int32
    const int*   batch = (const int*)d_in[2];    // [N] int32, sorted
    const float* W1  = (const float*)d_in[3];
    const float* b1  = (const float*)d_in[4];
    const float* W2  = (const float*)d_in[5];
    const float* b2  = (const float*)d_in[6];
    const float* W3  = (const float*)d_in[7];
    const float* b3  = (const float*)d_in[8];
    const float* W4  = (const float*)d_in[9];
    const float* b4  = (const float*)d_in[10];
    const float* Wf1 = (const float*)d_in[11];
    const float* bf1 = (const float*)d_in[12];
    const float* Wf2 = (const float*)d_in[13];
    const float* bf2 = (const float*)d_in[14];
    float* out = (float*)d_out;

    float *bufA, *bufB;
    cudaGetSymbolAddress((void**)&bufA, g_bufA);
    cudaGetSymbolAddress((void**)&bufB, g_bufB);

    const int TB = 256;
    int nb_nodes = (N_NODES + TB - 1) / TB;
    int nb_edges = (N_EDGES + TB - 1) / TB;

    // CSR build
    zero_deg_kernel<<<nb_nodes, TB>>>();
    count_kernel<<<nb_edges, TB>>>(ei);
    scan_kernel<<<1, 1024>>>();
    dinv_cursor_kernel<<<nb_nodes, TB>>>();
    fill_kernel<<<nb_edges, TB>>>(ei);

    // xs0 = x * dinv
    scale0_kernel<<<(N_NODES * 8 + TB - 1) / TB, TB>>>(x);

    const int AGG8_BLKS  = (N_NODES / 4 * 32 + TB - 1) / TB;   // 3125
    const int AGG24_BLKS = ((long)N_NODES * 32 + TB - 1) / TB; // 12500
    const int GEMM_BLKS  = (N_NODES + 63) / 64;                // 1563

    // layer 1  (aggregate in 32-dim, then 32->96 GEMM)
    agg_kernel<8><<<AGG8_BLKS, TB>>>(bufA, bufB);
    gemm_kernel<32, true><<<GEMM_BLKS, 128>>>(bufB, bufA, W1, b1);
    // layer 2
    agg_kernel<24><<<AGG24_BLKS, TB>>>(bufA, bufB);
    gemm_kernel<96, true><<<GEMM_BLKS, 128>>>(bufB, bufA, W2, b2);
    // layer 3
    agg_kernel<24><<<AGG24_BLKS, TB>>>(bufA, bufB);
    gemm_kernel<96, true><<<GEMM_BLKS, 128>>>(bufB, bufA, W3, b3);
    // layer 4 (no dinv scale on output)
    agg_kernel<24><<<AGG24_BLKS, TB>>>(bufA, bufB);
    gemm_kernel<96, false><<<GEMM_BLKS, 128>>>(bufB, bufA, W4, b4);

    // pool + MLP
    zero_pool_kernel<<<(N_GRAPHS * HID / 4 + TB - 1) / TB, TB>>>();
    int pool_warps = (N_NODES + 127) / 128;
    pool_kernel<<<(pool_warps * 32 + TB - 1) / TB, TB>>>(batch, bufA);
    mlp_kernel<<<N_GRAPHS / 4, 128>>>(Wf1, bf1, Wf2, bf2, out);
}